// round 3
// baseline (speedup 1.0000x reference)
#include <cuda_runtime.h>
#include <math.h>

#define BB 4
#define SS 1024
#define DD 1024
#define NH 16
#define DH 64
#define DI 4096
#define NROWS (BB*SS)

// ---------------- scratch (device globals; no allocation allowed) ----------------
__device__ float g_qkv[NROWS * 3 * DD];   // [B*S, 3072]
__device__ float g_vec[NROWS * DD];       // scrambled attn vec [B,S,H*dh]
__device__ float g_ao [NROWS * DD];       // attn_out = vec @ o_w
__device__ float g_o1 [NROWS * DD];       // after LN1 * mask
__device__ float g_c1 [NROWS * DI];       // conv1+relu
__device__ float g_c2 [NROWS * DD];       // conv2
__device__ int   g_len[BB];

// ---------------- mask decode: handle bool(uint8) / int32 / float32 ----------------
__global__ void decode_mask_kernel(const void* mask, int* lengths) {
    int b = threadIdx.x;
    if (b >= BB) return;
    const int* mi = (const int*)mask;
    int w0 = mi[0];                      // s=0 always valid (L >= S/2)
    bool bytes = (w0 == 0x01010101);     // packed bool bytes
    int cnt = 0;
    if (bytes) {
        const unsigned char* mb = (const unsigned char*)mask;
        for (int s = 0; s < SS; ++s) cnt += (mb[b * SS + s] != 0);
    } else {
        for (int s = 0; s < SS; ++s) cnt += (mi[b * SS + s] != 0); // works for int32 and f32 (1.0f != 0)
    }
    lengths[b] = cnt;
}

// ---------------- generic conv-as-GEMM ----------------
// out[(b,s), n] = act( sum_{k<ksize, c<Cin} in[b, s+k-pad, c] * W[(k*Cin+c)*Cout + n] + bias[n] )
// ksize=1 => plain GEMM. Tiles: BM=BN=128, BK=16, 256 threads, 8x8 micro-tile.
#define BM 128
#define BN 128
#define BK 16

__global__ __launch_bounds__(256, 2)
void gemm_conv_kernel(const float* __restrict__ A, const float* __restrict__ W,
                      const float* __restrict__ bias, float* __restrict__ C,
                      int Cin, int Cout, int ksize, int relu)
{
    __shared__ float As[BK][BM + 4];
    __shared__ float Bs[BK][BN + 4];

    const int tid = threadIdx.x;
    const int row0 = blockIdx.y * BM;
    const int col0 = blockIdx.x * BN;
    const int tm = tid >> 4;          // 0..15
    const int tn = tid & 15;          // 0..15

    // A loader: each thread loads 2 float4 of one row
    const int ar  = tid & 127;
    const int akc = (tid >> 7) * 8;   // 0 or 8
    const int grow = row0 + ar;
    const int b_  = grow / SS;
    const int s_  = grow - b_ * SS;
    // B loader: each thread loads 2 float4
    const int bcol = (tid & 31) * 4;
    const int bk0  = tid >> 5;        // 0..7 (and +8)

    const int pad = ksize >> 1;
    const int Ktot = ksize * Cin;

    float acc[8][8];
#pragma unroll
    for (int i = 0; i < 8; ++i)
#pragma unroll
        for (int j = 0; j < 8; ++j) acc[i][j] = 0.f;

    for (int k0 = 0; k0 < Ktot; k0 += BK) {
        const int ktap = k0 / Cin;            // constant over the BK tile (Cin % BK == 0)
        const int c0   = k0 - ktap * Cin;
        const int srow = s_ + ktap - pad;
        // --- load A tile (transposed into As) ---
        {
            float4 v0, v1;
            if (srow >= 0 && srow < SS) {
                const float* ap = A + ((size_t)b_ * SS + srow) * Cin + c0 + akc;
                v0 = *(const float4*)(ap);
                v1 = *(const float4*)(ap + 4);
            } else {
                v0 = make_float4(0.f, 0.f, 0.f, 0.f);
                v1 = v0;
            }
            As[akc + 0][ar] = v0.x; As[akc + 1][ar] = v0.y;
            As[akc + 2][ar] = v0.z; As[akc + 3][ar] = v0.w;
            As[akc + 4][ar] = v1.x; As[akc + 5][ar] = v1.y;
            As[akc + 6][ar] = v1.z; As[akc + 7][ar] = v1.w;
        }
        // --- load B tile ---
        {
            const float* wp = W + (size_t)(k0 + bk0) * Cout + col0 + bcol;
            *(float4*)&Bs[bk0    ][bcol] = *(const float4*)wp;
            *(float4*)&Bs[bk0 + 8][bcol] = *(const float4*)(wp + (size_t)8 * Cout);
        }
        __syncthreads();

#pragma unroll
        for (int kk = 0; kk < BK; ++kk) {
            float4 a0 = *(const float4*)&As[kk][tm * 8];
            float4 a1 = *(const float4*)&As[kk][tm * 8 + 4];
            float4 b0 = *(const float4*)&Bs[kk][tn * 8];
            float4 b1 = *(const float4*)&Bs[kk][tn * 8 + 4];
            float ra[8] = {a0.x, a0.y, a0.z, a0.w, a1.x, a1.y, a1.z, a1.w};
            float rb[8] = {b0.x, b0.y, b0.z, b0.w, b1.x, b1.y, b1.z, b1.w};
#pragma unroll
            for (int i = 0; i < 8; ++i)
#pragma unroll
                for (int j = 0; j < 8; ++j)
                    acc[i][j] = fmaf(ra[i], rb[j], acc[i][j]);
        }
        __syncthreads();
    }

    // epilogue
#pragma unroll
    for (int i = 0; i < 8; ++i) {
        const int r = row0 + tm * 8 + i;
        float* cp = C + (size_t)r * Cout + col0 + tn * 8;
        float v[8];
#pragma unroll
        for (int j = 0; j < 8; ++j) {
            float x = acc[i][j];
            if (bias) x += bias[col0 + tn * 8 + j];
            if (relu) x = fmaxf(x, 0.f);
            v[j] = x;
        }
        *(float4*)(cp)     = make_float4(v[0], v[1], v[2], v[3]);
        *(float4*)(cp + 4) = make_float4(v[4], v[5], v[6], v[7]);
    }
}

// ---------------- attention ----------------
// Faithful quirks: head i = b*H+h uses mask batch (i % B); softmax over PAD keys only
// (valid keys get -inf); +1.0 pad bias cancels in softmax. Output scramble:
// head i writes to batch (i % B), head-slot (i / B).
__global__ __launch_bounds__(128)
void attn_kernel(const float* __restrict__ qkv, const int* __restrict__ lengths,
                 float* __restrict__ vec)
{
    const int head = blockIdx.y;            // i = b*H + h
    const int b = head >> 4;
    const int h = head & 15;
    const int q0 = blockIdx.x * 16;
    const int L = lengths[head & 3];        // (b*H+h) % 4 == h % 4 == head % 4
    const int nk = SS - L;                  // 1..512

    __shared__ float qs[16][68];
    __shared__ float sc[16][512];
    __shared__ float kc[32][65];

    const int tid = threadIdx.x;

    // load Q tile: 16 rows x 64
    for (int idx = tid; idx < 16 * 16; idx += 128) {
        int qi = idx >> 4, dc = (idx & 15) * 4;
        float4 v = *(const float4*)&qkv[((size_t)(b * SS + q0 + qi)) * 3072 + h * 64 + dc];
        qs[qi][dc] = v.x; qs[qi][dc + 1] = v.y; qs[qi][dc + 2] = v.z; qs[qi][dc + 3] = v.w;
    }
    __syncthreads();

    const float scale = 0.125f; // 1/sqrt(64)

    // scores over pad keys
    for (int j0 = 0; j0 < nk; j0 += 32) {
        const int jn = min(32, nk - j0);
        __syncthreads();
        for (int idx = tid; idx < 32 * 16; idx += 128) {
            int kr = idx >> 4, dc = (idx & 15) * 4;
            if (kr < jn) {
                float4 v = *(const float4*)&qkv[((size_t)(b * SS + L + j0 + kr)) * 3072 + 1024 + h * 64 + dc];
                kc[kr][dc] = v.x; kc[kr][dc + 1] = v.y; kc[kr][dc + 2] = v.z; kc[kr][dc + 3] = v.w;
            }
        }
        __syncthreads();
        const int qi = tid & 15, ks = tid >> 4;
        for (int j = ks; j < jn; j += 8) {
            float d = 0.f;
#pragma unroll
            for (int dd = 0; dd < 64; ++dd) d = fmaf(qs[qi][dd], kc[j][dd], d);
            sc[qi][j0 + j] = d * scale;
        }
    }
    __syncthreads();

    // softmax per query over nk pad keys (the +1.0 bias is uniform -> cancels)
    if (tid < 16) {
        float m = -1e30f;
        for (int j = 0; j < nk; ++j) m = fmaxf(m, sc[tid][j]);
        float sum = 0.f;
        for (int j = 0; j < nk; ++j) { float e = expf(sc[tid][j] - m); sc[tid][j] = e; sum += e; }
        float inv = 1.f / sum;
        for (int j = 0; j < nk; ++j) sc[tid][j] *= inv;
    }
    __syncthreads();

    // prob @ V  (thread owns one query, 8 dims)
    const int qi2 = tid >> 3;
    const int d0  = (tid & 7) * 8;
    float acc[8];
#pragma unroll
    for (int i = 0; i < 8; ++i) acc[i] = 0.f;

    for (int j0 = 0; j0 < nk; j0 += 32) {
        const int jn = min(32, nk - j0);
        __syncthreads();
        for (int idx = tid; idx < 32 * 16; idx += 128) {
            int kr = idx >> 4, dc = (idx & 15) * 4;
            if (kr < jn) {
                float4 v = *(const float4*)&qkv[((size_t)(b * SS + L + j0 + kr)) * 3072 + 2048 + h * 64 + dc];
                kc[kr][dc] = v.x; kc[kr][dc + 1] = v.y; kc[kr][dc + 2] = v.z; kc[kr][dc + 3] = v.w;
            }
        }
        __syncthreads();
        for (int j = 0; j < jn; ++j) {
            float p = sc[qi2][j0 + j];
#pragma unroll
            for (int i = 0; i < 8; ++i) acc[i] = fmaf(p, kc[j][d0 + i], acc[i]);
        }
    }

    // scrambled write: batch = head % 4, head slot = head / 4
    const int ob = head & 3;
    const int oh = head >> 2;
    float* op = &vec[((size_t)(ob * SS) + q0 + qi2) * DD + oh * 64 + d0];
#pragma unroll
    for (int i = 0; i < 8; ++i) op[i] = acc[i];
}

// ---------------- layernorm (+ residual, + row mask) ----------------
__device__ __forceinline__ float block_sum256(float v, float* red) {
#pragma unroll
    for (int o = 16; o > 0; o >>= 1) v += __shfl_down_sync(0xffffffffu, v, o);
    const int lane = threadIdx.x & 31, w = threadIdx.x >> 5;
    if (lane == 0) red[w] = v;
    __syncthreads();
    if (w == 0) {
        v = (lane < 8) ? red[lane] : 0.f;
#pragma unroll
        for (int o = 4; o > 0; o >>= 1) v += __shfl_down_sync(0xffu, v, o);
        if (lane == 0) red[0] = v;
    }
    __syncthreads();
    float r = red[0];
    __syncthreads();
    return r;
}

__global__ __launch_bounds__(256)
void ln_kernel(const float* __restrict__ res, const float* __restrict__ y,
               const float* __restrict__ g, const float* __restrict__ bta,
               const int* __restrict__ lengths, float* __restrict__ out)
{
    __shared__ float buf[DD];
    __shared__ float red[32];
    const int row = blockIdx.x;
    const int b = row / SS, s = row - b * SS;
    const int tid = threadIdx.x;

    float lsum = 0.f;
    for (int c = tid; c < DD; c += 256) {
        float v = res[(size_t)row * DD + c] + y[(size_t)row * DD + c];
        buf[c] = v;
        lsum += v;
    }
    __syncthreads();
    const float mean = block_sum256(lsum, red) * (1.f / DD);

    float lvar = 0.f;
    for (int c = tid; c < DD; c += 256) {
        float d = buf[c] - mean;
        lvar += d * d;
    }
    const float var = block_sum256(lvar, red) * (1.f / DD);
    const float rstd = rsqrtf(var + 1e-3f);
    const float mrow = (s < lengths[b]) ? 1.f : 0.f;

    for (int c = tid; c < DD; c += 256)
        out[(size_t)row * DD + c] = ((buf[c] - mean) * rstd * g[c] + bta[c]) * mrow;
}

// ---------------- launch ----------------
extern "C" void kernel_launch(void* const* d_in, const int* in_sizes, int n_in,
                              void* d_out, int out_size)
{
    const float* dec   = (const float*)d_in[0];
    const void*  mask  = d_in[1];
    const float* qkv_w = (const float*)d_in[2];
    const float* qkv_b = (const float*)d_in[3];
    const float* o_w   = (const float*)d_in[4];
    const float* ln1g  = (const float*)d_in[5];
    const float* ln1b  = (const float*)d_in[6];
    const float* c1w   = (const float*)d_in[7];
    const float* c1b   = (const float*)d_in[8];
    const float* c2w   = (const float*)d_in[9];
    const float* c2b   = (const float*)d_in[10];
    const float* ln2g  = (const float*)d_in[11];
    const float* ln2b  = (const float*)d_in[12];
    float* out = (float*)d_out;

    static float *p_qkv = nullptr, *p_vec, *p_ao, *p_o1, *p_c1, *p_c2;
    static int* p_len;
    if (!p_qkv) {
        cudaGetSymbolAddress((void**)&p_qkv, g_qkv);
        cudaGetSymbolAddress((void**)&p_vec, g_vec);
        cudaGetSymbolAddress((void**)&p_ao,  g_ao);
        cudaGetSymbolAddress((void**)&p_o1,  g_o1);
        cudaGetSymbolAddress((void**)&p_c1,  g_c1);
        cudaGetSymbolAddress((void**)&p_c2,  g_c2);
        cudaGetSymbolAddress((void**)&p_len, g_len);
    }

    decode_mask_kernel<<<1, 32>>>(mask, p_len);

    // QKV: [4096,1024] @ [1024,3072] + b
    gemm_conv_kernel<<<dim3(3072 / BN, NROWS / BM), 256>>>(dec, qkv_w, qkv_b, p_qkv, DD, 3072, 1, 0);

    // attention (pad-keys-only softmax, scrambled output)
    attn_kernel<<<dim3(SS / 16, BB * NH), 128>>>(p_qkv, p_len, p_vec);

    // O-proj: [4096,1024] @ [1024,1024]
    gemm_conv_kernel<<<dim3(DD / BN, NROWS / BM), 256>>>(p_vec, o_w, nullptr, p_ao, DD, DD, 1, 0);

    // LN1(residual + attn_out) * mask
    ln_kernel<<<NROWS, 256>>>(dec, p_ao, ln1g, ln1b, p_len, p_o1);

    // conv1 (K=3, SAME) + relu: [4096, 3*1024] @ [3072, 4096]
    gemm_conv_kernel<<<dim3(DI / BN, NROWS / BM), 256>>>(p_o1, c1w, c1b, p_c1, DD, DI, 3, 1);

    // conv2 (K=3, SAME): [4096, 3*4096] @ [12288, 1024]
    gemm_conv_kernel<<<dim3(DD / BN, NROWS / BM), 256>>>(p_c1, c2w, c2b, p_c2, DI, DD, 3, 0);

    // LN2(out1 + core) * mask -> final output
    ln_kernel<<<NROWS, 256>>>(p_o1, p_c2, ln2g, ln2b, p_len, out);
}

// round 5
// speedup vs baseline: 1.1649x; 1.1649x over previous
#include <cuda_runtime.h>
#include <cuda_bf16.h>
#include <math.h>

#define BB 4
#define SS 1024
#define DD 1024
#define NH 16
#define DH 64
#define DI 4096
#define NROWS (BB*SS)

// ---------------- scratch (device globals; no allocation allowed) ----------------
__device__ float g_qkv[NROWS * 3 * DD];   // [B*S, 3072]
__device__ float g_vec[NROWS * DD];       // scrambled attn vec [B,S,H*dh]
__device__ float g_ao [NROWS * DD];       // attn_out = vec @ o_w
__device__ float g_o1 [NROWS * DD];       // after LN1 * mask
__device__ float g_c1 [NROWS * DI];       // conv1+relu
__device__ float g_c2 [NROWS * DD];       // conv2
__device__ int   g_len[BB];

// ---------------- mask decode: handle bool(uint8) / int32 / float32 ----------------
__global__ void decode_mask_kernel(const void* mask, int* lengths) {
    int b = threadIdx.x;
    if (b >= BB) return;
    const int* mi = (const int*)mask;
    int w0 = mi[0];                      // s=0 always valid (L >= S/2)
    bool bytes = (w0 == 0x01010101);     // packed bool bytes
    int cnt = 0;
    if (bytes) {
        const unsigned char* mb = (const unsigned char*)mask;
        for (int s = 0; s < SS; ++s) cnt += (mb[b * SS + s] != 0);
    } else {
        for (int s = 0; s < SS; ++s) cnt += (mi[b * SS + s] != 0);
    }
    lengths[b] = cnt;
}

// ---------------- bf16x3 split-precision tensor-core conv-GEMM ----------------
// C[(b,s), n] = act( sum_{k<ksize, c<Cin} A[b, s+k-pad, c] * W[(k*Cin+c)*Cout + n] + bias[n] )
// fp32 operands split into hi/lo bf16; 3 MMA passes (hi*hi + hi*lo + lo*hi), fp32 accum.
// Tiles: BM=BN=128, BK=32 (fp32), 256 threads, warp grid 2(M)x4(N), warp tile 64x32.

#define LDM4(R, addr) \
    asm volatile("ldmatrix.sync.aligned.m8n8.x4.shared.b16 {%0,%1,%2,%3}, [%4];" \
        : "=r"((R)[0]), "=r"((R)[1]), "=r"((R)[2]), "=r"((R)[3]) : "r"(addr))

#define MMA16816(c, a, b) \
    asm volatile("mma.sync.aligned.m16n8k16.row.col.f32.bf16.bf16.f32 " \
        "{%0,%1,%2,%3},{%4,%5,%6,%7},{%8,%9},{%0,%1,%2,%3};" \
        : "+f"((c)[0]), "+f"((c)[1]), "+f"((c)[2]), "+f"((c)[3]) \
        : "r"((a)[0]), "r"((a)[1]), "r"((a)[2]), "r"((a)[3]), "r"((b)[0]), "r"((b)[1]))

__device__ __forceinline__ unsigned pack_hi(float a, float b) {
    __nv_bfloat16 ha = __float2bfloat16(a), hb = __float2bfloat16(b);
    return ((unsigned)__bfloat16_as_ushort(hb) << 16) | (unsigned)__bfloat16_as_ushort(ha);
}
__device__ __forceinline__ unsigned pack_lo(float a, float b) {
    __nv_bfloat16 ha = __float2bfloat16(a), hb = __float2bfloat16(b);
    float ra = a - __bfloat162float(ha);
    float rb = b - __bfloat162float(hb);
    __nv_bfloat16 la = __float2bfloat16(ra), lb = __float2bfloat16(rb);
    return ((unsigned)__bfloat16_as_ushort(lb) << 16) | (unsigned)__bfloat16_as_ushort(la);
}

__global__ __launch_bounds__(256)
void gemm_mma_kernel(const float* __restrict__ A, const float* __restrict__ W,
                     const float* __restrict__ bias, float* __restrict__ C,
                     int Cin, int Cout, int ksize, int relu)
{
    // Each smem row = 128B: 32 hi halves | 32 lo halves, SW128-style unit swizzle.
    __shared__ __align__(16) unsigned char As[128 * 128];
    __shared__ __align__(16) unsigned char Bs[128 * 128];

    const int tid  = threadIdx.x;
    const int lane = tid & 31;
    const int wrp  = tid >> 5;
    const int wm   = (wrp >> 2) * 64;   // 0 or 64
    const int wn   = (wrp & 3) * 32;    // 0,32,64,96

    const int row0 = blockIdx.y * 128;
    const int col0 = blockIdx.x * 128;
    const int pad  = ksize >> 1;
    const int Ktot = ksize * Cin;

    // A loader mapping: thread -> (row, 16-float half)
    const int arow  = tid >> 1;
    const int ahalf = tid & 1;
    const int agrow = row0 + arow;
    const int ab    = agrow >> 10;          // batch
    const int asr   = agrow & 1023;         // seq
    // B loader mapping: thread -> (n, 16-k chunk)
    const int bn = tid & 127;
    const int bq = tid >> 7;                // 0 or 1

    const unsigned asb = (unsigned)__cvta_generic_to_shared(As);
    const unsigned bsb = (unsigned)__cvta_generic_to_shared(Bs);

    // ldmatrix base addresses (ks=0, hi plane); derive others via XOR 32 (ks) / 64 (lo)
    unsigned a_addr[4], b_addr[2];
#pragma unroll
    for (int mt = 0; mt < 4; ++mt) {
        int r = wm + mt * 16 + ((lane >> 3) & 1) * 8 + (lane & 7);
        unsigned u = (unsigned)(lane >> 4);
        a_addr[mt] = asb + r * 128 + ((u ^ (unsigned)(r & 7)) << 4);
    }
#pragma unroll
    for (int p = 0; p < 2; ++p) {
        int r = wn + p * 16 + (lane >> 4) * 8 + (lane & 7);
        unsigned u = (unsigned)((lane >> 3) & 1);
        b_addr[p] = bsb + r * 128 + ((u ^ (unsigned)(r & 7)) << 4);
    }

    float acc[16][4];
#pragma unroll
    for (int i = 0; i < 16; ++i)
#pragma unroll
        for (int j = 0; j < 4; ++j) acc[i][j] = 0.f;

    float av[16], bv[16];

    // ---- prologue: load first tiles into regs ----
    {
        const int k0 = 0;
        const int srow = asr + 0 - pad;
        if (srow >= 0 && srow < SS) {
            const float4* p = (const float4*)(A + ((size_t)(ab << 10) + srow) * Cin + ahalf * 16);
#pragma unroll
            for (int i = 0; i < 4; ++i) {
                float4 v = p[i];
                av[i*4+0] = v.x; av[i*4+1] = v.y; av[i*4+2] = v.z; av[i*4+3] = v.w;
            }
        } else {
#pragma unroll
            for (int i = 0; i < 16; ++i) av[i] = 0.f;
        }
        const float* wp = W + (size_t)(k0 + bq * 16) * Cout + col0 + bn;
#pragma unroll
        for (int kk = 0; kk < 16; ++kk) bv[kk] = wp[(size_t)kk * Cout];
    }

    for (int k0 = 0; k0 < Ktot; k0 += 32) {
        // ---- store staged regs to smem (hi/lo split) ----
        {
            const int r7a = arow & 7;
            uint4* abase = (uint4*)(As + arow * 128);
            unsigned h[8], l[8];
#pragma unroll
            for (int i = 0; i < 8; ++i) {
                h[i] = pack_hi(av[2*i], av[2*i+1]);
                l[i] = pack_lo(av[2*i], av[2*i+1]);
            }
            const int u0 = ahalf * 2;
            abase[(u0    ) ^ r7a] = make_uint4(h[0], h[1], h[2], h[3]);
            abase[(u0 + 1) ^ r7a] = make_uint4(h[4], h[5], h[6], h[7]);
            abase[(u0 + 4) ^ r7a] = make_uint4(l[0], l[1], l[2], l[3]);
            abase[(u0 + 5) ^ r7a] = make_uint4(l[4], l[5], l[6], l[7]);

            const int r7b = bn & 7;
            uint4* bbase = (uint4*)(Bs + bn * 128);
#pragma unroll
            for (int i = 0; i < 8; ++i) {
                h[i] = pack_hi(bv[2*i], bv[2*i+1]);
                l[i] = pack_lo(bv[2*i], bv[2*i+1]);
            }
            const int v0 = bq * 2;
            bbase[(v0    ) ^ r7b] = make_uint4(h[0], h[1], h[2], h[3]);
            bbase[(v0 + 1) ^ r7b] = make_uint4(h[4], h[5], h[6], h[7]);
            bbase[(v0 + 4) ^ r7b] = make_uint4(l[0], l[1], l[2], l[3]);
            bbase[(v0 + 5) ^ r7b] = make_uint4(l[4], l[5], l[6], l[7]);
        }
        __syncthreads();

        // ---- prefetch next tile into regs (overlaps with compute) ----
        const int kn = k0 + 32;
        if (kn < Ktot) {
            const int ktap = (kn < Cin) ? 0 : ((kn < 2 * Cin) ? 1 : 2);
            const int c0   = kn - ktap * Cin;
            const int srow = asr + ktap - pad;
            if (srow >= 0 && srow < SS) {
                const float4* p = (const float4*)(A + ((size_t)(ab << 10) + srow) * Cin + c0 + ahalf * 16);
#pragma unroll
                for (int i = 0; i < 4; ++i) {
                    float4 v = p[i];
                    av[i*4+0] = v.x; av[i*4+1] = v.y; av[i*4+2] = v.z; av[i*4+3] = v.w;
                }
            } else {
#pragma unroll
                for (int i = 0; i < 16; ++i) av[i] = 0.f;
            }
            const float* wp = W + (size_t)(kn + bq * 16) * Cout + col0 + bn;
#pragma unroll
            for (int kk = 0; kk < 16; ++kk) bv[kk] = wp[(size_t)kk * Cout];
        }

        // ---- compute: 2 k16-steps x 16 positions x 3 passes ----
#pragma unroll
        for (int ks = 0; ks < 2; ++ks) {
            unsigned Ah[4][4], Al[4][4], Bh[2][4], Bl[2][4];
#pragma unroll
            for (int mt = 0; mt < 4; ++mt) {
                unsigned ad = a_addr[mt] ^ (ks << 5);
                LDM4(Ah[mt], ad);
                LDM4(Al[mt], ad ^ 64u);
            }
#pragma unroll
            for (int p = 0; p < 2; ++p) {
                unsigned bd = b_addr[p] ^ (ks << 5);
                LDM4(Bh[p], bd);
                LDM4(Bl[p], bd ^ 64u);
            }
#pragma unroll
            for (int mt = 0; mt < 4; ++mt) {
#pragma unroll
                for (int nt = 0; nt < 4; ++nt) {
                    float* c = acc[mt * 4 + nt];
                    unsigned* bh = &Bh[nt >> 1][(nt & 1) * 2];
                    unsigned* bl = &Bl[nt >> 1][(nt & 1) * 2];
                    MMA16816(c, Ah[mt], bh);
                    MMA16816(c, Ah[mt], bl);
                    MMA16816(c, Al[mt], bh);
                }
            }
        }
        __syncthreads();
    }

    // ---- epilogue ----
#pragma unroll
    for (int mt = 0; mt < 4; ++mt) {
#pragma unroll
        for (int nt = 0; nt < 4; ++nt) {
            const float* c = acc[mt * 4 + nt];
            const int rr = row0 + wm + mt * 16 + (lane >> 2);
            const int cc = col0 + wn + nt * 8 + (lane & 3) * 2;
            float b0 = bias ? bias[cc]     : 0.f;
            float b1 = bias ? bias[cc + 1] : 0.f;
            float x0 = c[0] + b0, x1 = c[1] + b1, x2 = c[2] + b0, x3 = c[3] + b1;
            if (relu) { x0 = fmaxf(x0, 0.f); x1 = fmaxf(x1, 0.f); x2 = fmaxf(x2, 0.f); x3 = fmaxf(x3, 0.f); }
            *(float2*)&C[(size_t)rr * Cout + cc]       = make_float2(x0, x1);
            *(float2*)&C[(size_t)(rr + 8) * Cout + cc] = make_float2(x2, x3);
        }
    }
}

// ---------------- attention ----------------
// Faithful quirks: head i = b*H+h uses mask batch (i % B); softmax over PAD keys only
// (valid keys get -inf); +1.0 pad bias cancels in softmax. Output scramble:
// head i writes to batch (i % B), head-slot (i / B).
__global__ __launch_bounds__(128)
void attn_kernel(const float* __restrict__ qkv, const int* __restrict__ lengths,
                 float* __restrict__ vec)
{
    const int head = blockIdx.y;            // i = b*H + h
    const int b = head >> 4;
    const int h = head & 15;
    const int q0 = blockIdx.x * 16;
    const int L = lengths[head & 3];
    const int nk = SS - L;                  // 1..512

    __shared__ float qs[16][68];
    __shared__ float sc[16][512];
    __shared__ float kc[32][65];

    const int tid = threadIdx.x;

    for (int idx = tid; idx < 16 * 16; idx += 128) {
        int qi = idx >> 4, dc = (idx & 15) * 4;
        float4 v = *(const float4*)&qkv[((size_t)(b * SS + q0 + qi)) * 3072 + h * 64 + dc];
        qs[qi][dc] = v.x; qs[qi][dc + 1] = v.y; qs[qi][dc + 2] = v.z; qs[qi][dc + 3] = v.w;
    }
    __syncthreads();

    const float scale = 0.125f;

    for (int j0 = 0; j0 < nk; j0 += 32) {
        const int jn = min(32, nk - j0);
        __syncthreads();
        for (int idx = tid; idx < 32 * 16; idx += 128) {
            int kr = idx >> 4, dc = (idx & 15) * 4;
            if (kr < jn) {
                float4 v = *(const float4*)&qkv[((size_t)(b * SS + L + j0 + kr)) * 3072 + 1024 + h * 64 + dc];
                kc[kr][dc] = v.x; kc[kr][dc + 1] = v.y; kc[kr][dc + 2] = v.z; kc[kr][dc + 3] = v.w;
            }
        }
        __syncthreads();
        const int qi = tid & 15, ks = tid >> 4;
        for (int j = ks; j < jn; j += 8) {
            float d = 0.f;
#pragma unroll
            for (int dd = 0; dd < 64; ++dd) d = fmaf(qs[qi][dd], kc[j][dd], d);
            sc[qi][j0 + j] = d * scale;
        }
    }
    __syncthreads();

    if (tid < 16) {
        float m = -1e30f;
        for (int j = 0; j < nk; ++j) m = fmaxf(m, sc[tid][j]);
        float sum = 0.f;
        for (int j = 0; j < nk; ++j) { float e = expf(sc[tid][j] - m); sc[tid][j] = e; sum += e; }
        float inv = 1.f / sum;
        for (int j = 0; j < nk; ++j) sc[tid][j] *= inv;
    }
    __syncthreads();

    const int qi2 = tid >> 3;
    const int d0  = (tid & 7) * 8;
    float acc[8];
#pragma unroll
    for (int i = 0; i < 8; ++i) acc[i] = 0.f;

    for (int j0 = 0; j0 < nk; j0 += 32) {
        const int jn = min(32, nk - j0);
        __syncthreads();
        for (int idx = tid; idx < 32 * 16; idx += 128) {
            int kr = idx >> 4, dc = (idx & 15) * 4;
            if (kr < jn) {
                float4 v = *(const float4*)&qkv[((size_t)(b * SS + L + j0 + kr)) * 3072 + 2048 + h * 64 + dc];
                kc[kr][dc] = v.x; kc[kr][dc + 1] = v.y; kc[kr][dc + 2] = v.z; kc[kr][dc + 3] = v.w;
            }
        }
        __syncthreads();
        for (int j = 0; j < jn; ++j) {
            float p = sc[qi2][j0 + j];
#pragma unroll
            for (int i = 0; i < 8; ++i) acc[i] = fmaf(p, kc[j][d0 + i], acc[i]);
        }
    }

    const int ob = head & 3;
    const int oh = head >> 2;
    float* op = &vec[((size_t)(ob * SS) + q0 + qi2) * DD + oh * 64 + d0];
#pragma unroll
    for (int i = 0; i < 8; ++i) op[i] = acc[i];
}

// ---------------- layernorm (+ residual, + row mask) ----------------
__device__ __forceinline__ float block_sum256(float v, float* red) {
#pragma unroll
    for (int o = 16; o > 0; o >>= 1) v += __shfl_down_sync(0xffffffffu, v, o);
    const int lane = threadIdx.x & 31, w = threadIdx.x >> 5;
    if (lane == 0) red[w] = v;
    __syncthreads();
    if (w == 0) {
        v = (lane < 8) ? red[lane] : 0.f;
#pragma unroll
        for (int o = 4; o > 0; o >>= 1) v += __shfl_down_sync(0xffu, v, o);
        if (lane == 0) red[0] = v;
    }
    __syncthreads();
    float r = red[0];
    __syncthreads();
    return r;
}

__global__ __launch_bounds__(256)
void ln_kernel(const float* __restrict__ res, const float* __restrict__ y,
               const float* __restrict__ g, const float* __restrict__ bta,
               const int* __restrict__ lengths, float* __restrict__ out)
{
    __shared__ float buf[DD];
    __shared__ float red[32];
    const int row = blockIdx.x;
    const int b = row / SS, s = row - b * SS;
    const int tid = threadIdx.x;

    float lsum = 0.f;
    for (int c = tid; c < DD; c += 256) {
        float v = res[(size_t)row * DD + c] + y[(size_t)row * DD + c];
        buf[c] = v;
        lsum += v;
    }
    __syncthreads();
    const float mean = block_sum256(lsum, red) * (1.f / DD);

    float lvar = 0.f;
    for (int c = tid; c < DD; c += 256) {
        float d = buf[c] - mean;
        lvar += d * d;
    }
    const float var = block_sum256(lvar, red) * (1.f / DD);
    const float rstd = rsqrtf(var + 1e-3f);
    const float mrow = (s < lengths[b]) ? 1.f : 0.f;

    for (int c = tid; c < DD; c += 256)
        out[(size_t)row * DD + c] = ((buf[c] - mean) * rstd * g[c] + bta[c]) * mrow;
}

// ---------------- launch ----------------
extern "C" void kernel_launch(void* const* d_in, const int* in_sizes, int n_in,
                              void* d_out, int out_size)
{
    const float* dec   = (const float*)d_in[0];
    const void*  mask  = d_in[1];
    const float* qkv_w = (const float*)d_in[2];
    const float* qkv_b = (const float*)d_in[3];
    const float* o_w   = (const float*)d_in[4];
    const float* ln1g  = (const float*)d_in[5];
    const float* ln1b  = (const float*)d_in[6];
    const float* c1w   = (const float*)d_in[7];
    const float* c1b   = (const float*)d_in[8];
    const float* c2w   = (const float*)d_in[9];
    const float* c2b   = (const float*)d_in[10];
    const float* ln2g  = (const float*)d_in[11];
    const float* ln2b  = (const float*)d_in[12];
    float* out = (float*)d_out;

    static float *p_qkv = nullptr, *p_vec, *p_ao, *p_o1, *p_c1, *p_c2;
    static int* p_len;
    if (!p_qkv) {
        cudaGetSymbolAddress((void**)&p_qkv, g_qkv);
        cudaGetSymbolAddress((void**)&p_vec, g_vec);
        cudaGetSymbolAddress((void**)&p_ao,  g_ao);
        cudaGetSymbolAddress((void**)&p_o1,  g_o1);
        cudaGetSymbolAddress((void**)&p_c1,  g_c1);
        cudaGetSymbolAddress((void**)&p_c2,  g_c2);
        cudaGetSymbolAddress((void**)&p_len, g_len);
    }

    decode_mask_kernel<<<1, 32>>>(mask, p_len);

    // QKV: [4096,1024] @ [1024,3072] + b
    gemm_mma_kernel<<<dim3(3072 / 128, NROWS / 128), 256>>>(dec, qkv_w, qkv_b, p_qkv, DD, 3072, 1, 0);

    // attention (pad-keys-only softmax, scrambled output)
    attn_kernel<<<dim3(SS / 16, BB * NH), 128>>>(p_qkv, p_len, p_vec);

    // O-proj: [4096,1024] @ [1024,1024]
    gemm_mma_kernel<<<dim3(DD / 128, NROWS / 128), 256>>>(p_vec, o_w, nullptr, p_ao, DD, DD, 1, 0);

    // LN1(residual + attn_out) * mask
    ln_kernel<<<NROWS, 256>>>(dec, p_ao, ln1g, ln1b, p_len, p_o1);

    // conv1 (K=3, SAME) + relu: [4096, 3*1024] @ [3072, 4096]
    gemm_mma_kernel<<<dim3(DI / 128, NROWS / 128), 256>>>(p_o1, c1w, c1b, p_c1, DD, DI, 3, 1);

    // conv2 (K=3, SAME): [4096, 3*4096] @ [12288, 1024]
    gemm_mma_kernel<<<dim3(DD / 128, NROWS / 128), 256>>>(p_c1, c2w, c2b, p_c2, DI, DD, 3, 0);

    // LN2(out1 + core) * mask -> final output
    ln_kernel<<<NROWS, 256>>>(p_o1, p_c2, ln2g, ln2b, p_len, out);
}

// round 12
// speedup vs baseline: 1.8435x; 1.5825x over previous
#include <cuda_runtime.h>
#include <cuda_bf16.h>
#include <math.h>

#define BB 4
#define SS 1024
#define DD 1024
#define NH 16
#define DH 64
#define DI 4096
#define NROWS (BB*SS)

// ---------------- scratch (device globals; no allocation allowed) ----------------
__device__ float g_qkv[NROWS * 3 * DD];   // [B*S, 3072]
__device__ float g_vec[NROWS * DD];       // scrambled attn vec [B,S,H*dh]
__device__ float g_ao [NROWS * DD];       // attn_out = vec @ o_w
__device__ float g_o1 [NROWS * DD];       // after LN1 * mask
__device__ float g_c1 [NROWS * DI];       // conv1+relu
__device__ float g_c2 [NROWS * DD];       // conv2
__device__ int   g_len[BB];

// ---------------- mask decode: handle bool(uint8) / int32 / float32 ----------------
__global__ void decode_mask_kernel(const void* mask, int* lengths) {
    int b = threadIdx.x;
    if (b >= BB) return;
    const int* mi = (const int*)mask;
    int w0 = mi[0];                      // s=0 always valid (L >= S/2)
    bool bytes = (w0 == 0x01010101);     // packed bool bytes
    int cnt = 0;
    if (bytes) {
        const unsigned char* mb = (const unsigned char*)mask;
        for (int s = 0; s < SS; ++s) cnt += (mb[b * SS + s] != 0);
    } else {
        for (int s = 0; s < SS; ++s) cnt += (mi[b * SS + s] != 0);
    }
    lengths[b] = cnt;
}

// ---------------- bf16x3 split-precision tensor-core conv-GEMM ----------------
// C[(b,s), n] = act( sum_{k<ksize, c<Cin} A[b, s+k-pad, c] * W[(k*Cin+c)*Cout + n] + bias[n] )
// fp32 operands split into hi/lo bf16; 3 MMA passes (hi*hi + hi*lo + lo*hi), fp32 accum.
// Tiles: BM=BN=128, BK=32 (fp32), 256 threads, warp grid 2(M)x4(N), warp tile 64x32.

#define LDM4(R, addr) \
    asm volatile("ldmatrix.sync.aligned.m8n8.x4.shared.b16 {%0,%1,%2,%3}, [%4];" \
        : "=r"((R)[0]), "=r"((R)[1]), "=r"((R)[2]), "=r"((R)[3]) : "r"(addr))

#define MMA16816(c, a, b) \
    asm volatile("mma.sync.aligned.m16n8k16.row.col.f32.bf16.bf16.f32 " \
        "{%0,%1,%2,%3},{%4,%5,%6,%7},{%8,%9},{%0,%1,%2,%3};" \
        : "+f"((c)[0]), "+f"((c)[1]), "+f"((c)[2]), "+f"((c)[3]) \
        : "r"((a)[0]), "r"((a)[1]), "r"((a)[2]), "r"((a)[3]), "r"((b)[0]), "r"((b)[1]))

__device__ __forceinline__ unsigned pack_hi(float a, float b) {
    __nv_bfloat16 ha = __float2bfloat16(a), hb = __float2bfloat16(b);
    return ((unsigned)__bfloat16_as_ushort(hb) << 16) | (unsigned)__bfloat16_as_ushort(ha);
}
__device__ __forceinline__ unsigned pack_lo(float a, float b) {
    __nv_bfloat16 ha = __float2bfloat16(a), hb = __float2bfloat16(b);
    float ra = a - __bfloat162float(ha);
    float rb = b - __bfloat162float(hb);
    __nv_bfloat16 la = __float2bfloat16(ra), lb = __float2bfloat16(rb);
    return ((unsigned)__bfloat16_as_ushort(lb) << 16) | (unsigned)__bfloat16_as_ushort(la);
}

__global__ __launch_bounds__(256)
void gemm_mma_kernel(const float* __restrict__ A, const float* __restrict__ W,
                     const float* __restrict__ bias, float* __restrict__ C,
                     int Cin, int Cout, int ksize, int relu)
{
    // Each smem row = 128B: 32 hi halves | 32 lo halves, SW128-style unit swizzle.
    __shared__ __align__(16) unsigned char As[128 * 128];
    __shared__ __align__(16) unsigned char Bs[128 * 128];

    const int tid  = threadIdx.x;
    const int lane = tid & 31;
    const int wrp  = tid >> 5;
    const int wm   = (wrp >> 2) * 64;   // 0 or 64
    const int wn   = (wrp & 3) * 32;    // 0,32,64,96

    const int row0 = blockIdx.y * 128;
    const int col0 = blockIdx.x * 128;
    const int pad  = ksize >> 1;
    const int Ktot = ksize * Cin;

    // A loader mapping: thread -> (row, 16-float half)
    const int arow  = tid >> 1;
    const int ahalf = tid & 1;
    const int agrow = row0 + arow;
    const int ab    = agrow >> 10;          // batch
    const int asr   = agrow & 1023;         // seq
    // B loader mapping: thread -> (n, 16-k chunk)
    const int bn = tid & 127;
    const int bq = tid >> 7;                // 0 or 1

    const unsigned asb = (unsigned)__cvta_generic_to_shared(As);
    const unsigned bsb = (unsigned)__cvta_generic_to_shared(Bs);

    // ldmatrix base addresses (ks=0, hi plane); derive others via XOR 32 (ks) / 64 (lo)
    unsigned a_addr[4], b_addr[2];
#pragma unroll
    for (int mt = 0; mt < 4; ++mt) {
        int r = wm + mt * 16 + ((lane >> 3) & 1) * 8 + (lane & 7);
        unsigned u = (unsigned)(lane >> 4);
        a_addr[mt] = asb + r * 128 + ((u ^ (unsigned)(r & 7)) << 4);
    }
#pragma unroll
    for (int p = 0; p < 2; ++p) {
        int r = wn + p * 16 + (lane >> 4) * 8 + (lane & 7);
        unsigned u = (unsigned)((lane >> 3) & 1);
        b_addr[p] = bsb + r * 128 + ((u ^ (unsigned)(r & 7)) << 4);
    }

    float acc[16][4];
#pragma unroll
    for (int i = 0; i < 16; ++i)
#pragma unroll
        for (int j = 0; j < 4; ++j) acc[i][j] = 0.f;

    float av[16], bv[16];

    // ---- prologue: load first tiles into regs ----
    {
        const int k0 = 0;
        const int srow = asr + 0 - pad;
        if (srow >= 0 && srow < SS) {
            const float4* p = (const float4*)(A + ((size_t)(ab << 10) + srow) * Cin + ahalf * 16);
#pragma unroll
            for (int i = 0; i < 4; ++i) {
                float4 v = p[i];
                av[i*4+0] = v.x; av[i*4+1] = v.y; av[i*4+2] = v.z; av[i*4+3] = v.w;
            }
        } else {
#pragma unroll
            for (int i = 0; i < 16; ++i) av[i] = 0.f;
        }
        const float* wp = W + (size_t)(k0 + bq * 16) * Cout + col0 + bn;
#pragma unroll
        for (int kk = 0; kk < 16; ++kk) bv[kk] = wp[(size_t)kk * Cout];
    }

    for (int k0 = 0; k0 < Ktot; k0 += 32) {
        // ---- store staged regs to smem (hi/lo split) ----
        {
            const int r7a = arow & 7;
            uint4* abase = (uint4*)(As + arow * 128);
            unsigned h[8], l[8];
#pragma unroll
            for (int i = 0; i < 8; ++i) {
                h[i] = pack_hi(av[2*i], av[2*i+1]);
                l[i] = pack_lo(av[2*i], av[2*i+1]);
            }
            const int u0 = ahalf * 2;
            abase[(u0    ) ^ r7a] = make_uint4(h[0], h[1], h[2], h[3]);
            abase[(u0 + 1) ^ r7a] = make_uint4(h[4], h[5], h[6], h[7]);
            abase[(u0 + 4) ^ r7a] = make_uint4(l[0], l[1], l[2], l[3]);
            abase[(u0 + 5) ^ r7a] = make_uint4(l[4], l[5], l[6], l[7]);

            const int r7b = bn & 7;
            uint4* bbase = (uint4*)(Bs + bn * 128);
#pragma unroll
            for (int i = 0; i < 8; ++i) {
                h[i] = pack_hi(bv[2*i], bv[2*i+1]);
                l[i] = pack_lo(bv[2*i], bv[2*i+1]);
            }
            const int v0 = bq * 2;
            bbase[(v0    ) ^ r7b] = make_uint4(h[0], h[1], h[2], h[3]);
            bbase[(v0 + 1) ^ r7b] = make_uint4(h[4], h[5], h[6], h[7]);
            bbase[(v0 + 4) ^ r7b] = make_uint4(l[0], l[1], l[2], l[3]);
            bbase[(v0 + 5) ^ r7b] = make_uint4(l[4], l[5], l[6], l[7]);
        }
        __syncthreads();

        // ---- prefetch next tile into regs (overlaps with compute) ----
        const int kn = k0 + 32;
        if (kn < Ktot) {
            const int ktap = (kn < Cin) ? 0 : ((kn < 2 * Cin) ? 1 : 2);
            const int c0   = kn - ktap * Cin;
            const int srow = asr + ktap - pad;
            if (srow >= 0 && srow < SS) {
                const float4* p = (const float4*)(A + ((size_t)(ab << 10) + srow) * Cin + c0 + ahalf * 16);
#pragma unroll
                for (int i = 0; i < 4; ++i) {
                    float4 v = p[i];
                    av[i*4+0] = v.x; av[i*4+1] = v.y; av[i*4+2] = v.z; av[i*4+3] = v.w;
                }
            } else {
#pragma unroll
                for (int i = 0; i < 16; ++i) av[i] = 0.f;
            }
            const float* wp = W + (size_t)(kn + bq * 16) * Cout + col0 + bn;
#pragma unroll
            for (int kk = 0; kk < 16; ++kk) bv[kk] = wp[(size_t)kk * Cout];
        }

        // ---- compute: 2 k16-steps x 16 positions x 3 passes ----
#pragma unroll
        for (int ks = 0; ks < 2; ++ks) {
            unsigned Ah[4][4], Al[4][4], Bh[2][4], Bl[2][4];
#pragma unroll
            for (int mt = 0; mt < 4; ++mt) {
                unsigned ad = a_addr[mt] ^ (ks << 5);
                LDM4(Ah[mt], ad);
                LDM4(Al[mt], ad ^ 64u);
            }
#pragma unroll
            for (int p = 0; p < 2; ++p) {
                unsigned bd = b_addr[p] ^ (ks << 5);
                LDM4(Bh[p], bd);
                LDM4(Bl[p], bd ^ 64u);
            }
#pragma unroll
            for (int mt = 0; mt < 4; ++mt) {
#pragma unroll
                for (int nt = 0; nt < 4; ++nt) {
                    float* c = acc[mt * 4 + nt];
                    unsigned* bh = &Bh[nt >> 1][(nt & 1) * 2];
                    unsigned* bl = &Bl[nt >> 1][(nt & 1) * 2];
                    MMA16816(c, Ah[mt], bh);
                    MMA16816(c, Ah[mt], bl);
                    MMA16816(c, Al[mt], bh);
                }
            }
        }
        __syncthreads();
    }

    // ---- epilogue ----
#pragma unroll
    for (int mt = 0; mt < 4; ++mt) {
#pragma unroll
        for (int nt = 0; nt < 4; ++nt) {
            const float* c = acc[mt * 4 + nt];
            const int rr = row0 + wm + mt * 16 + (lane >> 2);
            const int cc = col0 + wn + nt * 8 + (lane & 3) * 2;
            float b0 = bias ? bias[cc]     : 0.f;
            float b1 = bias ? bias[cc + 1] : 0.f;
            float x0 = c[0] + b0, x1 = c[1] + b1, x2 = c[2] + b0, x3 = c[3] + b1;
            if (relu) { x0 = fmaxf(x0, 0.f); x1 = fmaxf(x1, 0.f); x2 = fmaxf(x2, 0.f); x3 = fmaxf(x3, 0.f); }
            *(float2*)&C[(size_t)rr * Cout + cc]       = make_float2(x0, x1);
            *(float2*)&C[(size_t)(rr + 8) * Cout + cc] = make_float2(x2, x3);
        }
    }
}

// ---------------- attention ----------------
// Faithful quirks: head i = b*H+h uses mask batch (i % B); softmax over PAD keys only
// (valid keys get -inf); +1.0 pad bias cancels in softmax. Output scramble:
// head i writes to batch (i % B), head-slot (i / B).
__global__ __launch_bounds__(128)
void attn_kernel(const float* __restrict__ qkv, const int* __restrict__ lengths,
                 float* __restrict__ vec)
{
    const int head = blockIdx.y;            // i = b*H + h
    const int b = head >> 4;
    const int h = head & 15;
    const int q0 = blockIdx.x * 16;
    const int L = lengths[head & 3];
    const int nk = SS - L;                  // 1..512

    __shared__ float qs[16][68];
    __shared__ float sc[16][512];
    __shared__ float kc[32][65];

    const int tid = threadIdx.x;

    for (int idx = tid; idx < 16 * 16; idx += 128) {
        int qi = idx >> 4, dc = (idx & 15) * 4;
        float4 v = *(const float4*)&qkv[((size_t)(b * SS + q0 + qi)) * 3072 + h * 64 + dc];
        qs[qi][dc] = v.x; qs[qi][dc + 1] = v.y; qs[qi][dc + 2] = v.z; qs[qi][dc + 3] = v.w;
    }
    __syncthreads();

    const float scale = 0.125f;

    for (int j0 = 0; j0 < nk; j0 += 32) {
        const int jn = min(32, nk - j0);
        __syncthreads();
        for (int idx = tid; idx < 32 * 16; idx += 128) {
            int kr = idx >> 4, dc = (idx & 15) * 4;
            if (kr < jn) {
                float4 v = *(const float4*)&qkv[((size_t)(b * SS + L + j0 + kr)) * 3072 + 1024 + h * 64 + dc];
                kc[kr][dc] = v.x; kc[kr][dc + 1] = v.y; kc[kr][dc + 2] = v.z; kc[kr][dc + 3] = v.w;
            }
        }
        __syncthreads();
        const int qi = tid & 15, ks = tid >> 4;
        for (int j = ks; j < jn; j += 8) {
            float d = 0.f;
#pragma unroll
            for (int dd = 0; dd < 64; ++dd) d = fmaf(qs[qi][dd], kc[j][dd], d);
            sc[qi][j0 + j] = d * scale;
        }
    }
    __syncthreads();

    if (tid < 16) {
        float m = -1e30f;
        for (int j = 0; j < nk; ++j) m = fmaxf(m, sc[tid][j]);
        float sum = 0.f;
        for (int j = 0; j < nk; ++j) { float e = expf(sc[tid][j] - m); sc[tid][j] = e; sum += e; }
        float inv = 1.f / sum;
        for (int j = 0; j < nk; ++j) sc[tid][j] *= inv;
    }
    __syncthreads();

    const int qi2 = tid >> 3;
    const int d0  = (tid & 7) * 8;
    float acc[8];
#pragma unroll
    for (int i = 0; i < 8; ++i) acc[i] = 0.f;

    for (int j0 = 0; j0 < nk; j0 += 32) {
        const int jn = min(32, nk - j0);
        __syncthreads();
        for (int idx = tid; idx < 32 * 16; idx += 128) {
            int kr = idx >> 4, dc = (idx & 15) * 4;
            if (kr < jn) {
                float4 v = *(const float4*)&qkv[((size_t)(b * SS + L + j0 + kr)) * 3072 + 2048 + h * 64 + dc];
                kc[kr][dc] = v.x; kc[kr][dc + 1] = v.y; kc[kr][dc + 2] = v.z; kc[kr][dc + 3] = v.w;
            }
        }
        __syncthreads();
        for (int j = 0; j < jn; ++j) {
            float p = sc[qi2][j0 + j];
#pragma unroll
            for (int i = 0; i < 8; ++i) acc[i] = fmaf(p, kc[j][d0 + i], acc[i]);
        }
    }

    const int ob = head & 3;
    const int oh = head >> 2;
    float* op = &vec[((size_t)(ob * SS) + q0 + qi2) * DD + oh * 64 + d0];
#pragma unroll
    for (int i = 0; i < 8; ++i) op[i] = acc[i];
}

// ---------------- layernorm (+ residual, + row mask) ----------------
__device__ __forceinline__ float block_sum256(float v, float* red) {
#pragma unroll
    for (int o = 16; o > 0; o >>= 1) v += __shfl_down_sync(0xffffffffu, v, o);
    const int lane = threadIdx.x & 31, w = threadIdx.x >> 5;
    if (lane == 0) red[w] = v;
    __syncthreads();
    if (w == 0) {
        v = (lane < 8) ? red[lane] : 0.f;
#pragma unroll
        for (int o = 4; o > 0; o >>= 1) v += __shfl_down_sync(0xffu, v, o);
        if (lane == 0) red[0] = v;
    }
    __syncthreads();
    float r = red[0];
    __syncthreads();
    return r;
}

__global__ __launch_bounds__(256)
void ln_kernel(const float* __restrict__ res, const float* __restrict__ y,
               const float* __restrict__ g, const float* __restrict__ bta,
               const int* __restrict__ lengths, float* __restrict__ out)
{
    __shared__ float buf[DD];
    __shared__ float red[32];
    const int row = blockIdx.x;
    const int b = row / SS, s = row - b * SS;
    const int tid = threadIdx.x;

    float lsum = 0.f;
    for (int c = tid; c < DD; c += 256) {
        float v = res[(size_t)row * DD + c] + y[(size_t)row * DD + c];
        buf[c] = v;
        lsum += v;
    }
    __syncthreads();
    const float mean = block_sum256(lsum, red) * (1.f / DD);

    float lvar = 0.f;
    for (int c = tid; c < DD; c += 256) {
        float d = buf[c] - mean;
        lvar += d * d;
    }
    const float var = block_sum256(lvar, red) * (1.f / DD);
    const float rstd = rsqrtf(var + 1e-3f);
    const float mrow = (s < lengths[b]) ? 1.f : 0.f;

    for (int c = tid; c < DD; c += 256)
        out[(size_t)row * DD + c] = ((buf[c] - mean) * rstd * g[c] + bta[c]) * mrow;
}

// ---------------- launch ----------------
extern "C" void kernel_launch(void* const* d_in, const int* in_sizes, int n_in,
                              void* d_out, int out_size)
{
    const float* dec   = (const float*)d_in[0];
    const void*  mask  = d_in[1];
    const float* qkv_w = (const float*)d_in[2];
    const float* qkv_b = (const float*)d_in[3];
    const float* o_w   = (const float*)d_in[4];
    const float* ln1g  = (const float*)d_in[5];
    const float* ln1b  = (const float*)d_in[6];
    const float* c1w   = (const float*)d_in[7];
    const float* c1b   = (const float*)d_in[8];
    const float* c2w   = (const float*)d_in[9];
    const float* c2b   = (const float*)d_in[10];
    const float* ln2g  = (const float*)d_in[11];
    const float* ln2b  = (const float*)d_in[12];
    float* out = (float*)d_out;

    static float *p_qkv = nullptr, *p_vec, *p_ao, *p_o1, *p_c1, *p_c2;
    static int* p_len;
    if (!p_qkv) {
        cudaGetSymbolAddress((void**)&p_qkv, g_qkv);
        cudaGetSymbolAddress((void**)&p_vec, g_vec);
        cudaGetSymbolAddress((void**)&p_ao,  g_ao);
        cudaGetSymbolAddress((void**)&p_o1,  g_o1);
        cudaGetSymbolAddress((void**)&p_c1,  g_c1);
        cudaGetSymbolAddress((void**)&p_c2,  g_c2);
        cudaGetSymbolAddress((void**)&p_len, g_len);
    }

    decode_mask_kernel<<<1, 32>>>(mask, p_len);

    // QKV: [4096,1024] @ [1024,3072] + b
    gemm_mma_kernel<<<dim3(3072 / 128, NROWS / 128), 256>>>(dec, qkv_w, qkv_b, p_qkv, DD, 3072, 1, 0);

    // attention (pad-keys-only softmax, scrambled output)
    attn_kernel<<<dim3(SS / 16, BB * NH), 128>>>(p_qkv, p_len, p_vec);

    // O-proj: [4096,1024] @ [1024,1024]
    gemm_mma_kernel<<<dim3(DD / 128, NROWS / 128), 256>>>(p_vec, o_w, nullptr, p_ao, DD, DD, 1, 0);

    // LN1(residual + attn_out) * mask
    ln_kernel<<<NROWS, 256>>>(dec, p_ao, ln1g, ln1b, p_len, p_o1);

    // conv1 (K=3, SAME) + relu: [4096, 3*1024] @ [3072, 4096]
    gemm_mma_kernel<<<dim3(DI / 128, NROWS / 128), 256>>>(p_o1, c1w, c1b, p_c1, DD, DI, 3, 1);

    // conv2 (K=3, SAME): [4096, 3*4096] @ [12288, 1024]
    gemm_mma_kernel<<<dim3(DD / 128, NROWS / 128), 256>>>(p_c1, c2w, c2b, p_c2, DI, DD, 3, 0);

    // LN2(out1 + core) * mask -> final output
    ln_kernel<<<NROWS, 256>>>(p_o1, p_c2, ln2g, ln2b, p_len, out);
}